// round 7
// baseline (speedup 1.0000x reference)
#include <cuda_runtime.h>
#include <cuda_bf16.h>
#include <cstdint>

#define DEV_INLINE __device__ __forceinline__

constexpr int N_PTS  = 131072;
constexpr int K_CL   = 256;
constexpr int D_DIM  = 32;

constexpr int TILE_M = 128;                 // points per CTA
constexpr int KTOT   = 576;                 // 528 pairs + 32 linear + 16 pad
constexpr int NCH    = KTOT / 32;           // 18 chunks of 32 k-columns
constexpr int U_CHUNK = K_CL * 64;          // 256 rows x 64B = 16384
constexpr int F_CHUNK = TILE_M * 64;        // 128 rows x 64B = 8192
constexpr int XD_STRIDE = 69;               // floats; 69%32=5 -> conflict-free rotated reads

// ---------------- device-global scratch ----------------
__device__ __align__(128) unsigned char U_g[NCH * U_CHUNK]; // pre-swizzled bf16 B operand
__device__ float g_g[K_CL];              // g'_k = log|w_k| + 0.5 logdet(A_k) - 0.5 c^T A c

// ---------------- helpers ----------------
DEV_INLINE uint32_t smem_u32(const void* p) {
    uint32_t a;
    asm("{ .reg .u64 t; cvta.to.shared.u64 t, %1; cvt.u32.u64 %0, t; }" : "=r"(a) : "l"(p));
    return a;
}
// row-dependent swizzle for 64B rows: rotate 16B chunks by (row>>1)&3
DEV_INLINE uint32_t swz(uint32_t c, uint32_t row) { return c ^ ((row & 6u) << 3); }

DEV_INLINE void sts_v4(uint32_t a, uint32_t v0, uint32_t v1, uint32_t v2, uint32_t v3) {
    asm volatile("st.shared.v4.b32 [%0], {%1,%2,%3,%4};"
                 :: "r"(a), "r"(v0), "r"(v1), "r"(v2), "r"(v3) : "memory");
}
DEV_INLINE void cp_async16(uint32_t dst, const void* src) {
    asm volatile("cp.async.cg.shared.global [%0], [%1], 16;"
                 :: "r"(dst), "l"(__cvta_generic_to_global(src)) : "memory");
}
#define CP_COMMIT() asm volatile("cp.async.commit_group;" ::: "memory")
#define CP_WAIT0()  asm volatile("cp.async.wait_group 0;" ::: "memory")
#define CP_WAIT1()  asm volatile("cp.async.wait_group 1;" ::: "memory")
#define BAR_SYNC(id, cnt) asm volatile("bar.sync %0, %1;" :: "r"(id), "r"(cnt) : "memory")

DEV_INLINE void ldsm4(uint32_t* r, uint32_t addr) {
    asm volatile("ldmatrix.sync.aligned.m8n8.x4.shared.b16 {%0,%1,%2,%3}, [%4];"
                 : "=r"(r[0]), "=r"(r[1]), "=r"(r[2]), "=r"(r[3]) : "r"(addr));
}

DEV_INLINE void mma16816(float* c, const uint32_t* a, uint32_t b0, uint32_t b1) {
    asm volatile(
        "mma.sync.aligned.m16n8k16.row.col.f32.bf16.bf16.f32 "
        "{%0,%1,%2,%3}, {%4,%5,%6,%7}, {%8,%9}, {%0,%1,%2,%3};"
        : "+f"(c[0]), "+f"(c[1]), "+f"(c[2]), "+f"(c[3])
        : "r"(a[0]), "r"(a[1]), "r"(a[2]), "r"(a[3]), "r"(b0), "r"(b1));
}

// ---------------- per-cluster prep ----------------
__global__ void k_prep(const float* __restrict__ centers,
                       const float* __restrict__ S,
                       const float* __restrict__ w) {
    __shared__ float Ssh[D_DIM * D_DIM];
    __shared__ float Ash[D_DIM * 33];
    __shared__ float csh[D_DIM];
    __shared__ float msh[D_DIM];
    int k = blockIdx.x, t = threadIdx.x;

    #pragma unroll
    for (int q = 0; q < 4; q++) Ssh[t + 256 * q] = S[k * 1024 + t + 256 * q];
    if (t < 32) csh[t] = centers[k * 32 + t];
    __syncthreads();

    #pragma unroll
    for (int q = 0; q < 4; q++) {
        int idx = t + 256 * q;
        int d = idx >> 5, f = idx & 31;
        float a = 0.f;
        #pragma unroll
        for (int e = 0; e < 32; e++) a += Ssh[d * 32 + e] * Ssh[f * 32 + e];
        Ash[d * 33 + f] = a;
    }
    __syncthreads();

    if (t < 32) {
        float m = 0.f;
        #pragma unroll
        for (int f = 0; f < 32; f++) m += Ash[t * 33 + f] * csh[f];
        msh[t] = m;
    }
    __syncthreads();

    // U entries (bf16, swizzled SMEM image), circular-offset pair layout:
    //  chunk c<16 , col j : c==0 ? -0.5 A_jj : -A_{j,(j+c)&31}
    //  chunk 16, col j<16 : -A_{j,j+16} ; col j>=16 : m_{j-16}
    //  chunk 17, col j<16 : m_{j+16}   ; col j>=16 : 0
    for (int p = t; p < KTOT; p += 256) {
        int c = p >> 5, j = p & 31;
        float val;
        if (c == 0)       val = -0.5f * Ash[j * 33 + j];
        else if (c < 16)  val = -Ash[j * 33 + ((j + c) & 31)];
        else if (c == 16) val = (j < 16) ? -Ash[j * 33 + j + 16] : msh[j - 16];
        else              val = (j < 16) ? msh[j + 16] : 0.f;
        uint32_t off = (uint32_t)c * U_CHUNK + (uint32_t)k * 64 + swz((uint32_t)j * 2, (uint32_t)k);
        *reinterpret_cast<__nv_bfloat16*>(U_g + off) = __float2bfloat16(val);
    }
    __syncthreads();

    if (t < 32) {
        float cAc = msh[t] * csh[t];
        #pragma unroll
        for (int o = 16; o > 0; o >>= 1) cAc += __shfl_xor_sync(0xffffffff, cAc, o);
        // warp Cholesky (SPD), lane = row
        float halflogdet = 0.f;
        for (int j = 0; j < 32; j++) {
            float ljj = sqrtf(Ash[j * 33 + j]);
            halflogdet += logf(ljj);
            float lij = (t > j) ? Ash[t * 33 + j] / ljj : 0.f;
            if (t > j) Ash[t * 33 + j] = lij;
            __syncwarp();
            if (t > j) {
                for (int c2 = j + 1; c2 <= t; c2++)
                    Ash[t * 33 + c2] -= lij * Ash[c2 * 33 + j];
            }
            __syncwarp();
        }
        if (t == 0)
            g_g[k] = logf(fabsf(w[k]) + 1e-37f) + halflogdet - 0.5f * cAc;
    }
}

// ---------------- main fused GEMM + logsumexp ----------------
constexpr int SMEM_U   = 0;                          // 3 x 16384 = 49152
constexpr int SMEM_F   = 49152;                      // 2 x 8192 = 16384
constexpr int SMEM_X   = 65536;                      // 128 x 69 f32 = 35328
constexpr int SMEM_G   = 100864;                     // 256 f32
constexpr int SMEM_P   = 101888;                     // 128 x 4 f32
constexpr int SMEM_RED = 103936;                     // 8 max + 8 sum floats
constexpr int SMEM_DYN = 104000 + 1024;

__global__ __launch_bounds__(512, 1)
void k_main(const float* __restrict__ points,
            const float* __restrict__ wts,
            const float* __restrict__ thr_p,
            float* __restrict__ out) {
    extern __shared__ char smem_raw[];
    char* smem = (char*)(((uintptr_t)smem_raw + 1023) & ~(uintptr_t)1023);
    uint32_t sb = smem_u32(smem);
    int tid = threadIdx.x;
    int wid = tid >> 5, lane = tid & 31;
    int g = lane >> 2, t4 = lane & 3;
    int warp_r = wid >> 2, warp_c = wid & 3;   // rows 32*warp_r, cols 64*warp_c (16 warps)
    int i0 = blockIdx.x * TILE_M;

    float* Xd = (float*)(smem + SMEM_X);       // [128][69], cols 0..31 = x, 32..39 = wrap dup
    float* gs = (float*)(smem + SMEM_G);
    float* redm = (float*)(smem + SMEM_RED);
    float* reds = (float*)(smem + SMEM_RED + 32);

    // loads: X tile (duplicated wrap cols), g', weights
    #pragma unroll
    for (int q = 0; q < 8; q++) {
        int lin = tid + 512 * q;               // 0..4095
        Xd[(lin >> 5) * XD_STRIDE + (lin & 31)] = points[(size_t)i0 * 32 + lin];
    }
    for (int lin = tid; lin < 1024; lin += 512) {
        int r = lin >> 3, cq = lin & 7;
        Xd[r * XD_STRIDE + 32 + cq] = points[(size_t)i0 * 32 + r * 32 + cq];
    }
    if (tid < 256) {
        float gv = g_g[tid];
        gs[tid] = gv;
        float wv = fabsf(wts[tid]);
        #pragma unroll
        for (int o = 16; o > 0; o >>= 1) {
            gv = fmaxf(gv, __shfl_xor_sync(0xffffffff, gv, o));
            wv += __shfl_xor_sync(0xffffffff, wv, o);
        }
        if (lane == 0) { redm[wid] = gv; reds[wid] = wv; }
    }
    float thrv = thr_p[0];

    // F generation mapping: F-group = warps sharing warp_r (barrier 1+warp_r).
    // Within group, wg_tid = warp_c*32 + lane covers rows [warp_r*32, +32), quarter fq.
    int wg_tid = warp_c * 32 + lane;
    int fr = warp_r * 32 + (wg_tid >> 2), fq = wg_tid & 3;
    const float* srow = Xd + fr * XD_STRIDE;
    uint32_t gen_base0 = (uint32_t)fr * 64 + (((uint32_t)fq * 16) ^ (((uint32_t)fr & 6u) << 3));

    // U load mapping: U-group = warps sharing warp_c (barrier 5+warp_c).
    // Within group, ug_tid = warp_r*32 + lane covers rows [warp_c*64, +64), 32B halves.
    int ug_tid = warp_r * 32 + lane;
    uint32_t u_off = (uint32_t)(warp_c * 64 + (ug_tid >> 1)) * 64 + (uint32_t)(ug_tid & 1) * 32;

    // ldmatrix address precompute
    uint32_t offA[2][2], offB[2][4];
    {
        uint32_t lane15 = (uint32_t)(lane & 15);
        uint32_t colA = (uint32_t)(lane & 16);
        #pragma unroll
        for (int rt = 0; rt < 2; rt++) {
            uint32_t row = (uint32_t)(warp_r * 32 + rt * 16) + lane15;
            uint32_t m = (row & 6u) << 3;
            #pragma unroll
            for (int ks = 0; ks < 2; ks++)
                offA[ks][rt] = row * 64 + (((uint32_t)ks * 32 + colA) ^ m);
        }
        uint32_t colB = ((uint32_t)(lane & 8)) << 1;
        #pragma unroll
        for (int pr = 0; pr < 4; pr++) {
            uint32_t n = (uint32_t)(warp_c * 64 + pr * 16) + (((uint32_t)lane >> 1) & 8u) + (uint32_t)(lane & 7);
            uint32_t m = (n & 6u) << 3;
            #pragma unroll
            for (int ks = 0; ks < 2; ks++)
                offB[ks][pr] = n * 64 + (((uint32_t)ks * 32 + colB) ^ m);
        }
    }

    // own 8 x-values in registers (after Xd written; full sync below before use)
    __syncthreads();
    float xself[8];
    #pragma unroll
    for (int jj = 0; jj < 8; jj++) xself[jj] = srow[fq * 8 + jj];

    auto gen_F = [&](int c, int stage) {
        uint32_t base = sb + SMEM_F + (uint32_t)stage * F_CHUNK + gen_base0;
        int cc = (c >= 16) ? 16 : c;
        int b = (fq * 8 + cc) & 31;
        float xo[8];
        #pragma unroll
        for (int jj = 0; jj < 8; jj++) xo[jj] = srow[b + jj];   // conflict-free (stride 69)
        float v[8];
        if (c < 16) {
            #pragma unroll
            for (int jj = 0; jj < 8; jj++) v[jj] = xself[jj] * xo[jj];
        } else if (c == 16) {
            #pragma unroll
            for (int jj = 0; jj < 8; jj++) v[jj] = (fq < 2) ? xself[jj] * xo[jj] : xo[jj];
        } else {
            #pragma unroll
            for (int jj = 0; jj < 8; jj++) v[jj] = (fq < 2) ? xo[jj] : 0.f;
        }
        uint32_t o[4];
        #pragma unroll
        for (int q = 0; q < 4; q++) {
            __nv_bfloat162 p2 = __floats2bfloat162_rn(v[2 * q], v[2 * q + 1]);
            o[q] = *(uint32_t*)&p2;
        }
        sts_v4(base, o[0], o[1], o[2], o[3]);
    };
    auto load_U = [&](int c, int stage) {
        const unsigned char* src = U_g + (size_t)c * U_CHUNK + u_off;
        uint32_t dst = sb + SMEM_U + (uint32_t)stage * U_CHUNK + u_off;
        cp_async16(dst, src);
        cp_async16(dst + 16, src + 16);
        CP_COMMIT();
    };

    float acc[2][8][4];
    #pragma unroll
    for (int a = 0; a < 2; a++)
        #pragma unroll
        for (int b = 0; b < 8; b++)
            #pragma unroll
            for (int j = 0; j < 4; j++) acc[a][b][j] = 0.f;

    // prologue: F(0) generated, U(0),U(1) in flight
    gen_F(0, 0);
    load_U(0, 0);
    load_U(1, 1);
    __syncthreads();   // covers F(0) visibility + Xd + gs

    int barF = 1 + warp_r, barU = 5 + warp_c;

    for (int c = 0; c < NCH; c++) {
        int fs = c & 1;
        int us = c % 3;
        // wait for U(c) data, then group-local visibility barriers
        if (c + 1 < NCH) { CP_WAIT1(); } else { CP_WAIT0(); }
        BAR_SYNC(barU, 128);
        if (c > 0) BAR_SYNC(barF, 128);

        uint32_t fb = sb + SMEM_F + (uint32_t)fs * F_CHUNK;
        uint32_t ub = sb + SMEM_U + (uint32_t)us * U_CHUNK;

        // A fragments for both k-steps
        uint32_t fA[2][2][4];
        #pragma unroll
        for (int ks = 0; ks < 2; ks++)
            #pragma unroll
            for (int rt = 0; rt < 2; rt++)
                ldsm4(fA[ks][rt], fb + offA[ks][rt]);

        // first B fragment
        uint32_t fBc[4], fBn[4];
        ldsm4(fBc, ub + offB[0][0]);

        if (c + 1 < NCH) gen_F(c + 1, fs ^ 1);
        if (c + 2 < NCH) load_U(c + 2, (c + 2) % 3);

        #pragma unroll
        for (int step = 0; step < 8; step++) {
            int ks = step >> 2, pr = step & 3;
            if (step < 7) {
                int ns = step + 1;
                ldsm4(fBn, ub + offB[ns >> 2][ns & 3]);
            }
            #pragma unroll
            for (int rt = 0; rt < 2; rt++) {
                mma16816(acc[rt][2 * pr],     fA[ks][rt], fBc[0], fBc[1]);
                mma16816(acc[rt][2 * pr + 1], fA[ks][rt], fBc[2], fBc[3]);
            }
            #pragma unroll
            for (int j = 0; j < 4; j++) fBc[j] = fBn[j];
        }
    }

    // -------- epilogue: exp-sum, reduce, log --------
    float Cv = fmaxf(fmaxf(fmaxf(redm[0], redm[1]), fmaxf(redm[2], redm[3])),
                     fmaxf(fmaxf(redm[4], redm[5]), fmaxf(redm[6], redm[7])));
    float LW = logf(reds[0] + reds[1] + reds[2] + reds[3] +
                    reds[4] + reds[5] + reds[6] + reds[7] + 1e-30f);

    float* part = (float*)(smem + SMEM_P);
    #pragma unroll
    for (int rt = 0; rt < 2; rt++) {
        float e_lo = 0.f, e_hi = 0.f;
        #pragma unroll
        for (int ct = 0; ct < 8; ct++) {
            int n0 = warp_c * 64 + ct * 8 + t4 * 2;
            float g0 = gs[n0] - Cv, g1 = gs[n0 + 1] - Cv;
            e_lo += __expf(acc[rt][ct][0] + g0) + __expf(acc[rt][ct][1] + g1);
            e_hi += __expf(acc[rt][ct][2] + g0) + __expf(acc[rt][ct][3] + g1);
        }
        e_lo += __shfl_xor_sync(0xffffffff, e_lo, 1);
        e_lo += __shfl_xor_sync(0xffffffff, e_lo, 2);
        e_hi += __shfl_xor_sync(0xffffffff, e_hi, 1);
        e_hi += __shfl_xor_sync(0xffffffff, e_hi, 2);
        if (t4 == 0) {
            int r = warp_r * 32 + rt * 16 + g;
            part[r * 4 + warp_c] = e_lo;
            part[(r + 8) * 4 + warp_c] = e_hi;
        }
    }
    __syncthreads();
    if (tid < 128) {
        float ssum = part[tid * 4] + part[tid * 4 + 1] + part[tid * 4 + 2] + part[tid * 4 + 3];
        out[i0 + tid] = logf(ssum) + Cv - LW - thrv;
    }
}

// ---------------- launch ----------------
extern "C" void kernel_launch(void* const* d_in, const int* in_sizes, int n_in,
                              void* d_out, int out_size) {
    const float* points  = (const float*)d_in[0];
    const float* centers = (const float*)d_in[1];
    const float* covs    = (const float*)d_in[2];
    const float* weights = (const float*)d_in[3];
    const float* thresh  = (const float*)d_in[4];
    float* out = (float*)d_out;

    int n = in_sizes[0] / D_DIM;     // 131072
    int grid = n / TILE_M;           // 1024

    k_prep<<<K_CL, 256>>>(centers, covs, weights);

    cudaFuncSetAttribute(k_main, cudaFuncAttributeMaxDynamicSharedMemorySize, SMEM_DYN);
    k_main<<<grid, 512, SMEM_DYN>>>(points, weights, thresh, out);
}

// round 8
// speedup vs baseline: 1.1239x; 1.1239x over previous
#include <cuda_runtime.h>
#include <cuda_bf16.h>
#include <cstdint>

#define DEV_INLINE __device__ __forceinline__

constexpr int N_PTS = 131072;
constexpr int K_CL  = 256;
constexpr int D_DIM = 32;
constexpr int NCH   = 18;     // 16 circular-pair chunks + 2 tail chunks

// ---------------- device-global scratch ----------------
// U in MMA-fragment-major layout: [chunk][n-tile 0..31][lane 0..31] x uint4
//   lane l serves n = T*8 + (l>>2); uint4 = {ks0:(b0,b1), ks1:(b0,b1)} bf16x2 each
__device__ __align__(128) uint32_t U_lg[NCH * 32 * 32 * 4];
__device__ float g_g[K_CL];           // g'_k = log|w_k| + 0.5 logdet(A_k) - 0.5 c^T A c
__device__ float C_g, LW_g;           // max g', log sum|w|
__device__ float part_g[2 * N_PTS];   // per-half partial exp-sums

// ---------------- helpers ----------------
DEV_INLINE uint32_t mulb2(uint32_t a, uint32_t b) {
    uint32_t d; asm("mul.rn.bf16x2 %0,%1,%2;" : "=r"(d) : "r"(a), "r"(b)); return d;
}
DEV_INLINE uint32_t prmt5432(uint32_t a, uint32_t b) {
    uint32_t d; asm("prmt.b32 %0,%1,%2,0x5432;" : "=r"(d) : "r"(a), "r"(b)); return d;
}
DEV_INLINE void mma16816(float* c, const uint32_t* a, uint32_t b0, uint32_t b1) {
    asm volatile(
        "mma.sync.aligned.m16n8k16.row.col.f32.bf16.bf16.f32 "
        "{%0,%1,%2,%3}, {%4,%5,%6,%7}, {%8,%9}, {%0,%1,%2,%3};"
        : "+f"(c[0]), "+f"(c[1]), "+f"(c[2]), "+f"(c[3])
        : "r"(a[0]), "r"(a[1]), "r"(a[2]), "r"(a[3]), "r"(b0), "r"(b1));
}

// ---------------- per-cluster prep ----------------
// k-slot permutation: kslot = 2q + r + 8m  <->  logical d = 8q + 2m + r
// chunk c<16 : coeff(d, (d+c)&31) : c==0 ? -0.5 A_dd : -A
// chunk 16   : q<2 (d<16): -A[d][d+16] ; q>=2: m_{d-16}
// chunk 17   : q<2: m_{d+16} ; else 0
__global__ void k_prep(const float* __restrict__ centers,
                       const float* __restrict__ S,
                       const float* __restrict__ w) {
    __shared__ float Ssh[D_DIM * D_DIM];
    __shared__ float Ash[D_DIM * 33];
    __shared__ float csh[D_DIM];
    __shared__ float msh[D_DIM];
    int k = blockIdx.x, t = threadIdx.x;

    #pragma unroll
    for (int qq = 0; qq < 4; qq++) Ssh[t + 256 * qq] = S[k * 1024 + t + 256 * qq];
    if (t < 32) csh[t] = centers[k * 32 + t];
    __syncthreads();

    #pragma unroll
    for (int qq = 0; qq < 4; qq++) {
        int idx = t + 256 * qq;
        int d = idx >> 5, f = idx & 31;
        float a = 0.f;
        #pragma unroll
        for (int e = 0; e < 32; e++) a += Ssh[d * 32 + e] * Ssh[f * 32 + e];
        Ash[d * 33 + f] = a;
    }
    __syncthreads();

    if (t < 32) {
        float m = 0.f;
        #pragma unroll
        for (int f = 0; f < 32; f++) m += Ash[t * 33 + f] * csh[f];
        msh[t] = m;
    }
    __syncthreads();

    // write U fragment-major: 18 chunks x 16 u32 per cluster = 288 u32
    for (int p = t; p < 288; p += 256) {
        int c = p >> 4, q = (p >> 2) & 3, m = p & 3;
        float v[2];
        #pragma unroll
        for (int r = 0; r < 2; r++) {
            int d = 8 * q + 2 * m + r;
            float val;
            if (c == 0)       val = -0.5f * Ash[d * 33 + d];
            else if (c < 16)  val = -Ash[d * 33 + ((d + c) & 31)];
            else if (c == 16) val = (q < 2) ? -Ash[d * 33 + d + 16] : msh[d - 16];
            else              val = (q < 2) ? msh[d + 16] : 0.f;
            v[r] = val;
        }
        __nv_bfloat162 b2 = __floats2bfloat162_rn(v[0], v[1]);
        U_lg[(((c * 32) + (k >> 3)) * 32 + (k & 7) * 4 + q) * 4 + m] = *(uint32_t*)&b2;
    }
    __syncthreads();

    if (t < 32) {
        float cAc = msh[t] * csh[t];
        #pragma unroll
        for (int o = 16; o > 0; o >>= 1) cAc += __shfl_xor_sync(0xffffffff, cAc, o);
        // warp Cholesky (SPD), lane = row
        float halflogdet = 0.f;
        for (int j = 0; j < 32; j++) {
            float ljj = sqrtf(Ash[j * 33 + j]);
            halflogdet += logf(ljj);
            float lij = (t > j) ? Ash[t * 33 + j] / ljj : 0.f;
            if (t > j) Ash[t * 33 + j] = lij;
            __syncwarp();
            if (t > j) {
                for (int c2 = j + 1; c2 <= t; c2++)
                    Ash[t * 33 + c2] -= lij * Ash[c2 * 33 + j];
            }
            __syncwarp();
        }
        if (t == 0)
            g_g[k] = logf(fabsf(w[k]) + 1e-37f) + halflogdet - 0.5f * cAc;
    }
}

__global__ void k_stats(const float* __restrict__ w) {
    __shared__ float sm[256], sw[256];
    int t = threadIdx.x;
    sm[t] = g_g[t];
    sw[t] = fabsf(w[t]);
    __syncthreads();
    for (int s = 128; s > 0; s >>= 1) {
        if (t < s) { sm[t] = fmaxf(sm[t], sm[t + s]); sw[t] += sw[t + s]; }
        __syncthreads();
    }
    if (t == 0) { C_g = sm[0]; LW_g = logf(sw[0] + 1e-30f); }
}

// ---------------- main: register-resident F, direct-LDG B, syncless mainloop ----------------
// grid = 2048: blockIdx>>1 = point tile (128 pts), blockIdx&1 = cluster half (128 n)
// 16 warps as 4x4: warp_r rows 32*warp_r.. (+32), warp_c cols 32*warp_c within half.
__global__ __launch_bounds__(512, 1)
void k_main(const float* __restrict__ points) {
    __shared__ float part[512];
    int tid = threadIdx.x, wid = tid >> 5, lane = tid & 31;
    int g = lane >> 2, q = lane & 3;
    int warp_r = wid >> 2, warp_c = wid & 3;
    int khalf = blockIdx.x & 1;
    int i0 = (blockIdx.x >> 1) * 128;

    // xself / xrot: 4 rows x 4 bf16x2 (x[8q .. 8q+7] per row), register-resident
    uint32_t xs[4][4], xr[4][4];
    #pragma unroll
    for (int j = 0; j < 4; j++) {
        int R = warp_r * 32 + (j >> 1) * 16 + (j & 1) * 8 + g;
        const float4* pp = (const float4*)(points + (size_t)(i0 + R) * 32 + q * 8);
        float4 f0 = __ldg(pp), f1 = __ldg(pp + 1);
        __nv_bfloat162 b;
        b = __floats2bfloat162_rn(f0.x, f0.y); xs[j][0] = *(uint32_t*)&b;
        b = __floats2bfloat162_rn(f0.z, f0.w); xs[j][1] = *(uint32_t*)&b;
        b = __floats2bfloat162_rn(f1.x, f1.y); xs[j][2] = *(uint32_t*)&b;
        b = __floats2bfloat162_rn(f1.z, f1.w); xs[j][3] = *(uint32_t*)&b;
        #pragma unroll
        for (int m = 0; m < 4; m++) xr[j][m] = xs[j][m];
    }

    // B pointer (uint4 units): tile stride 32, chunk stride 32*32
    const uint4* ub = ((const uint4*)U_lg) + (size_t)(khalf * 16 + warp_c * 4) * 32 + lane;
    uint4 rb[4];
    #pragma unroll
    for (int t = 0; t < 4; t++) rb[t] = __ldg(ub + t * 32);

    float acc[2][4][4];
    #pragma unroll
    for (int a = 0; a < 2; a++)
        #pragma unroll
        for (int b = 0; b < 4; b++)
            #pragma unroll
            for (int j = 0; j < 4; j++) acc[a][b][j] = 0.f;

    int srcl = (lane & ~3) | ((q + 1) & 3);

    #define DO_CHUNK(prod, c) do {                                              \
        _Pragma("unroll")                                                        \
        for (int t = 0; t < 4; t++) {                                            \
            uint4 b = rb[t];                                                     \
            if ((c) + 1 < NCH) rb[t] = __ldg(ub + (((c) + 1) * 32 + t) * 32);    \
            { uint32_t A[4] = {prod[0][0], prod[1][0], prod[0][1], prod[1][1]};  \
              mma16816(acc[0][t], A, b.x, b.y); }                                \
            { uint32_t A[4] = {prod[0][2], prod[1][2], prod[0][3], prod[1][3]};  \
              mma16816(acc[0][t], A, b.z, b.w); }                                \
            { uint32_t A[4] = {prod[2][0], prod[3][0], prod[2][1], prod[3][1]};  \
              mma16816(acc[1][t], A, b.x, b.y); }                                \
            { uint32_t A[4] = {prod[2][2], prod[3][2], prod[2][3], prod[3][3]};  \
              mma16816(acc[1][t], A, b.z, b.w); }                                \
        }                                                                        \
    } while (0)

    for (int c = 0; c < 16; c++) {
        uint32_t prod[4][4];
        #pragma unroll
        for (int j = 0; j < 4; j++)
            #pragma unroll
            for (int m = 0; m < 4; m++) prod[j][m] = mulb2(xs[j][m], xr[j][m]);
        DO_CHUNK(prod, c);
        // rotate xrot by one element (distributed across q-lanes)
        #pragma unroll
        for (int j = 0; j < 4; j++) {
            uint32_t inc = __shfl_sync(0xffffffffu, xr[j][0], srcl);
            xr[j][0] = prmt5432(xr[j][0], xr[j][1]);
            xr[j][1] = prmt5432(xr[j][1], xr[j][2]);
            xr[j][2] = prmt5432(xr[j][2], xr[j][3]);
            xr[j][3] = prmt5432(xr[j][3], inc);
        }
    }
    {   // chunk 16: q<2: pairs (d, d+16); q>=2: linear x_{d-16} (times m in U)
        uint32_t prod[4][4];
        #pragma unroll
        for (int j = 0; j < 4; j++)
            #pragma unroll
            for (int m = 0; m < 4; m++)
                prod[j][m] = (q < 2) ? mulb2(xs[j][m], xr[j][m]) : xr[j][m];
        DO_CHUNK(prod, 16);
    }
    {   // chunk 17: q<2: linear x_{d+16}; q>=2: zero
        uint32_t prod[4][4];
        #pragma unroll
        for (int j = 0; j < 4; j++)
            #pragma unroll
            for (int m = 0; m < 4; m++)
                prod[j][m] = (q < 2) ? xr[j][m] : 0u;
        DO_CHUNK(prod, 17);
    }
    #undef DO_CHUNK

    // -------- epilogue: exp-sum over this half's 128 clusters --------
    float C = C_g;
    int n0 = khalf * 128 + warp_c * 32;
    float g0[4], g1[4];
    #pragma unroll
    for (int t = 0; t < 4; t++) {
        g0[t] = g_g[n0 + t * 8 + q * 2]     - C;
        g1[t] = g_g[n0 + t * 8 + q * 2 + 1] - C;
    }
    #pragma unroll
    for (int rt = 0; rt < 2; rt++)
        #pragma unroll
        for (int h = 0; h < 2; h++) {
            float e = 0.f;
            #pragma unroll
            for (int t = 0; t < 4; t++) {
                e += __expf(acc[rt][t][2 * h]     + g0[t]);
                e += __expf(acc[rt][t][2 * h + 1] + g1[t]);
            }
            e += __shfl_xor_sync(0xffffffffu, e, 1);
            e += __shfl_xor_sync(0xffffffffu, e, 2);
            if (q == 0)
                part[(warp_r * 32 + rt * 16 + h * 8 + g) * 4 + warp_c] = e;
        }
    __syncthreads();
    if (tid < 128) {
        float s = part[tid * 4] + part[tid * 4 + 1] + part[tid * 4 + 2] + part[tid * 4 + 3];
        part_g[(size_t)khalf * N_PTS + i0 + tid] = s;
    }
}

__global__ void k_combine(const float* __restrict__ thr, float* __restrict__ out) {
    int i = blockIdx.x * 256 + threadIdx.x;
    out[i] = logf(part_g[i] + part_g[N_PTS + i]) + C_g - LW_g - thr[0];
}

// ---------------- launch ----------------
extern "C" void kernel_launch(void* const* d_in, const int* in_sizes, int n_in,
                              void* d_out, int out_size) {
    const float* points  = (const float*)d_in[0];
    const float* centers = (const float*)d_in[1];
    const float* covs    = (const float*)d_in[2];
    const float* weights = (const float*)d_in[3];
    const float* thresh  = (const float*)d_in[4];
    float* out = (float*)d_out;

    int n = in_sizes[0] / D_DIM;     // 131072

    k_prep<<<K_CL, 256>>>(centers, covs, weights);
    k_stats<<<1, 256>>>(weights);
    k_main<<<(n / 128) * 2, 512>>>(points);
    k_combine<<<n / 256, 256>>>(thresh, out);
}

// round 9
// speedup vs baseline: 1.1246x; 1.0006x over previous
#include <cuda_runtime.h>
#include <cuda_bf16.h>
#include <cstdint>

#define DEV_INLINE __device__ __forceinline__

constexpr int N_PTS = 131072;
constexpr int K_CL  = 256;
constexpr int D_DIM = 32;
constexpr int NCH   = 18;     // 16 circular-pair chunks + 2 tail chunks

// ---------------- device-global scratch ----------------
// U in MMA-fragment-major layout: [chunk][n-tile 0..31][lane 0..31] x uint4
//   lane l serves n = T*8 + (l>>2); uint4 = {ks0:(b0,b1), ks1:(b0,b1)} bf16x2 each
__device__ __align__(128) uint32_t U_lg[NCH * 32 * 32 * 4];
__device__ float g_g[K_CL];           // g'_k = log|w_k| + 0.5 logdet(A_k) - 0.5 c^T A c
__device__ float C_g, LW_g;           // max g', log sum|w|
__device__ float part_g[2 * N_PTS];   // per-half partial exp-sums

// ---------------- helpers ----------------
DEV_INLINE uint32_t mulb2(uint32_t a, uint32_t b) {
    uint32_t d; asm("mul.rn.bf16x2 %0,%1,%2;" : "=r"(d) : "r"(a), "r"(b)); return d;
}
DEV_INLINE uint32_t prmt5432(uint32_t a, uint32_t b) {
    uint32_t d; asm("prmt.b32 %0,%1,%2,0x5432;" : "=r"(d) : "r"(a), "r"(b)); return d;
}
DEV_INLINE void mma16816(float* c, const uint32_t* a, uint32_t b0, uint32_t b1) {
    asm volatile(
        "mma.sync.aligned.m16n8k16.row.col.f32.bf16.bf16.f32 "
        "{%0,%1,%2,%3}, {%4,%5,%6,%7}, {%8,%9}, {%0,%1,%2,%3};"
        : "+f"(c[0]), "+f"(c[1]), "+f"(c[2]), "+f"(c[3])
        : "r"(a[0]), "r"(a[1]), "r"(a[2]), "r"(a[3]), "r"(b0), "r"(b1));
}

// ---------------- per-cluster prep ----------------
// k-slot permutation: kslot = 2q + r + 8m  <->  logical d = 8q + 2m + r
// chunk c<16 : coeff(d, (d+c)&31) : c==0 ? -0.5 A_dd : -A
// chunk 16   : q<2 (d<16): -A[d][d+16] ; q>=2: m_{d-16}
// chunk 17   : q<2: m_{d+16} ; else 0
__global__ void k_prep(const float* __restrict__ centers,
                       const float* __restrict__ S,
                       const float* __restrict__ w) {
    __shared__ float Ssh[D_DIM * D_DIM];
    __shared__ float Ash[D_DIM * 33];
    __shared__ float csh[D_DIM];
    __shared__ float msh[D_DIM];
    int k = blockIdx.x, t = threadIdx.x;

    #pragma unroll
    for (int qq = 0; qq < 4; qq++) Ssh[t + 256 * qq] = S[k * 1024 + t + 256 * qq];
    if (t < 32) csh[t] = centers[k * 32 + t];
    __syncthreads();

    #pragma unroll
    for (int qq = 0; qq < 4; qq++) {
        int idx = t + 256 * qq;
        int d = idx >> 5, f = idx & 31;
        float a = 0.f;
        #pragma unroll
        for (int e = 0; e < 32; e++) a += Ssh[d * 32 + e] * Ssh[f * 32 + e];
        Ash[d * 33 + f] = a;
    }
    __syncthreads();

    if (t < 32) {
        float m = 0.f;
        #pragma unroll
        for (int f = 0; f < 32; f++) m += Ash[t * 33 + f] * csh[f];
        msh[t] = m;
    }
    __syncthreads();

    // write U fragment-major: 18 chunks x 16 u32 per cluster = 288 u32
    for (int p = t; p < 288; p += 256) {
        int c = p >> 4, q = (p >> 2) & 3, m = p & 3;
        float v[2];
        #pragma unroll
        for (int r = 0; r < 2; r++) {
            int d = 8 * q + 2 * m + r;
            float val;
            if (c == 0)       val = -0.5f * Ash[d * 33 + d];
            else if (c < 16)  val = -Ash[d * 33 + ((d + c) & 31)];
            else if (c == 16) val = (q < 2) ? -Ash[d * 33 + d + 16] : msh[d - 16];
            else              val = (q < 2) ? msh[d + 16] : 0.f;
            v[r] = val;
        }
        __nv_bfloat162 b2 = __floats2bfloat162_rn(v[0], v[1]);
        U_lg[(((c * 32) + (k >> 3)) * 32 + (k & 7) * 4 + q) * 4 + m] = *(uint32_t*)&b2;
    }
    __syncthreads();

    if (t < 32) {
        float cAc = msh[t] * csh[t];
        #pragma unroll
        for (int o = 16; o > 0; o >>= 1) cAc += __shfl_xor_sync(0xffffffff, cAc, o);
        // warp Cholesky (SPD), lane = row
        float halflogdet = 0.f;
        for (int j = 0; j < 32; j++) {
            float ljj = sqrtf(Ash[j * 33 + j]);
            halflogdet += logf(ljj);
            float lij = (t > j) ? Ash[t * 33 + j] / ljj : 0.f;
            if (t > j) Ash[t * 33 + j] = lij;
            __syncwarp();
            if (t > j) {
                for (int c2 = j + 1; c2 <= t; c2++)
                    Ash[t * 33 + c2] -= lij * Ash[c2 * 33 + j];
            }
            __syncwarp();
        }
        if (t == 0)
            g_g[k] = logf(fabsf(w[k]) + 1e-37f) + halflogdet - 0.5f * cAc;
    }
}

__global__ void k_stats(const float* __restrict__ w) {
    __shared__ float sm[256], sw[256];
    int t = threadIdx.x;
    sm[t] = g_g[t];
    sw[t] = fabsf(w[t]);
    __syncthreads();
    for (int s = 128; s > 0; s >>= 1) {
        if (t < s) { sm[t] = fmaxf(sm[t], sm[t + s]); sw[t] += sw[t + s]; }
        __syncthreads();
    }
    if (t == 0) { C_g = sm[0]; LW_g = logf(sw[0] + 1e-30f); }
}

// ---------------- main: register-resident F, direct-LDG B, syncless mainloop ----------------
// grid = 2048: blockIdx>>1 = point tile (128 pts), blockIdx&1 = cluster half (128 n)
// 16 warps as 4x4: warp_r rows 32*warp_r.. (+32), warp_c cols 32*warp_c within half.
__global__ __launch_bounds__(512, 1)
void k_main(const float* __restrict__ points) {
    __shared__ float part[512];
    int tid = threadIdx.x, wid = tid >> 5, lane = tid & 31;
    int g = lane >> 2, q = lane & 3;
    int warp_r = wid >> 2, warp_c = wid & 3;
    int khalf = blockIdx.x & 1;
    int i0 = (blockIdx.x >> 1) * 128;

    // xself / xrot: 4 rows x 4 bf16x2 (x[8q .. 8q+7] per row), register-resident
    uint32_t xs[4][4], xr[4][4];
    #pragma unroll
    for (int j = 0; j < 4; j++) {
        int R = warp_r * 32 + (j >> 1) * 16 + (j & 1) * 8 + g;
        const float4* pp = (const float4*)(points + (size_t)(i0 + R) * 32 + q * 8);
        float4 f0 = __ldg(pp), f1 = __ldg(pp + 1);
        __nv_bfloat162 b;
        b = __floats2bfloat162_rn(f0.x, f0.y); xs[j][0] = *(uint32_t*)&b;
        b = __floats2bfloat162_rn(f0.z, f0.w); xs[j][1] = *(uint32_t*)&b;
        b = __floats2bfloat162_rn(f1.x, f1.y); xs[j][2] = *(uint32_t*)&b;
        b = __floats2bfloat162_rn(f1.z, f1.w); xs[j][3] = *(uint32_t*)&b;
        #pragma unroll
        for (int m = 0; m < 4; m++) xr[j][m] = xs[j][m];
    }

    // B pointer (uint4 units): tile stride 32, chunk stride 32*32
    const uint4* ub = ((const uint4*)U_lg) + (size_t)(khalf * 16 + warp_c * 4) * 32 + lane;
    uint4 rb[4];
    #pragma unroll
    for (int t = 0; t < 4; t++) rb[t] = __ldg(ub + t * 32);

    float acc[2][4][4];
    #pragma unroll
    for (int a = 0; a < 2; a++)
        #pragma unroll
        for (int b = 0; b < 4; b++)
            #pragma unroll
            for (int j = 0; j < 4; j++) acc[a][b][j] = 0.f;

    int srcl = (lane & ~3) | ((q + 1) & 3);

    #define DO_CHUNK(prod, c) do {                                              \
        _Pragma("unroll")                                                        \
        for (int t = 0; t < 4; t++) {                                            \
            uint4 b = rb[t];                                                     \
            if ((c) + 1 < NCH) rb[t] = __ldg(ub + (((c) + 1) * 32 + t) * 32);    \
            { uint32_t A[4] = {prod[0][0], prod[1][0], prod[0][1], prod[1][1]};  \
              mma16816(acc[0][t], A, b.x, b.y); }                                \
            { uint32_t A[4] = {prod[0][2], prod[1][2], prod[0][3], prod[1][3]};  \
              mma16816(acc[0][t], A, b.z, b.w); }                                \
            { uint32_t A[4] = {prod[2][0], prod[3][0], prod[2][1], prod[3][1]};  \
              mma16816(acc[1][t], A, b.x, b.y); }                                \
            { uint32_t A[4] = {prod[2][2], prod[3][2], prod[2][3], prod[3][3]};  \
              mma16816(acc[1][t], A, b.z, b.w); }                                \
        }                                                                        \
    } while (0)

    for (int c = 0; c < 16; c++) {
        uint32_t prod[4][4];
        #pragma unroll
        for (int j = 0; j < 4; j++)
            #pragma unroll
            for (int m = 0; m < 4; m++) prod[j][m] = mulb2(xs[j][m], xr[j][m]);
        DO_CHUNK(prod, c);
        // rotate xrot by one element (distributed across q-lanes)
        #pragma unroll
        for (int j = 0; j < 4; j++) {
            uint32_t inc = __shfl_sync(0xffffffffu, xr[j][0], srcl);
            xr[j][0] = prmt5432(xr[j][0], xr[j][1]);
            xr[j][1] = prmt5432(xr[j][1], xr[j][2]);
            xr[j][2] = prmt5432(xr[j][2], xr[j][3]);
            xr[j][3] = prmt5432(xr[j][3], inc);
        }
    }
    {   // chunk 16: q<2: pairs (d, d+16); q>=2: linear x_{d-16} (times m in U)
        uint32_t prod[4][4];
        #pragma unroll
        for (int j = 0; j < 4; j++)
            #pragma unroll
            for (int m = 0; m < 4; m++)
                prod[j][m] = (q < 2) ? mulb2(xs[j][m], xr[j][m]) : xr[j][m];
        DO_CHUNK(prod, 16);
    }
    {   // chunk 17: q<2: linear x_{d+16}; q>=2: zero
        uint32_t prod[4][4];
        #pragma unroll
        for (int j = 0; j < 4; j++)
            #pragma unroll
            for (int m = 0; m < 4; m++)
                prod[j][m] = (q < 2) ? xr[j][m] : 0u;
        DO_CHUNK(prod, 17);
    }
    #undef DO_CHUNK

    // -------- epilogue: exp-sum over this half's 128 clusters --------
    float C = C_g;
    int n0 = khalf * 128 + warp_c * 32;
    float g0[4], g1[4];
    #pragma unroll
    for (int t = 0; t < 4; t++) {
        g0[t] = g_g[n0 + t * 8 + q * 2]     - C;
        g1[t] = g_g[n0 + t * 8 + q * 2 + 1] - C;
    }
    #pragma unroll
    for (int rt = 0; rt < 2; rt++)
        #pragma unroll
        for (int h = 0; h < 2; h++) {
            float e = 0.f;
            #pragma unroll
            for (int t = 0; t < 4; t++) {
                e += __expf(acc[rt][t][2 * h]     + g0[t]);
                e += __expf(acc[rt][t][2 * h + 1] + g1[t]);
            }
            e += __shfl_xor_sync(0xffffffffu, e, 1);
            e += __shfl_xor_sync(0xffffffffu, e, 2);
            if (q == 0)
                part[(warp_r * 32 + rt * 16 + h * 8 + g) * 4 + warp_c] = e;
        }
    __syncthreads();
    if (tid < 128) {
        float s = part[tid * 4] + part[tid * 4 + 1] + part[tid * 4 + 2] + part[tid * 4 + 3];
        part_g[(size_t)khalf * N_PTS + i0 + tid] = s;
    }
}

__global__ void k_combine(const float* __restrict__ thr, float* __restrict__ out) {
    int i = blockIdx.x * 256 + threadIdx.x;
    out[i] = logf(part_g[i] + part_g[N_PTS + i]) + C_g - LW_g - thr[0];
}

// ---------------- launch ----------------
extern "C" void kernel_launch(void* const* d_in, const int* in_sizes, int n_in,
                              void* d_out, int out_size) {
    const float* points  = (const float*)d_in[0];
    const float* centers = (const float*)d_in[1];
    const float* covs    = (const float*)d_in[2];
    const float* weights = (const float*)d_in[3];
    const float* thresh  = (const float*)d_in[4];
    float* out = (float*)d_out;

    int n = in_sizes[0] / D_DIM;     // 131072

    k_prep<<<K_CL, 256>>>(centers, covs, weights);
    k_stats<<<1, 256>>>(weights);
    k_main<<<(n / 128) * 2, 512>>>(points);
    k_combine<<<n / 256, 256>>>(thresh, out);
}